// round 2
// baseline (speedup 1.0000x reference)
#include <cuda_runtime.h>
#include <cooperative_groups.h>
#include <math.h>
#include <stdint.h>

namespace cg = cooperative_groups;

#define S_LEN 4096
#define D_DIM 300
#define HU    150
#define HH    300      // biLSTM concat dim
#define Z_DIM 600      // 4*HU
#define NSYN  4

// ---------------- scratch (static device memory; no allocation) ----------------
__device__ float g_emb[S_LEN * D_DIM];
__device__ float g_Zf[S_LEN * Z_DIM];
__device__ float g_Zb[S_LEN * Z_DIM];
__device__ float g_hidden[S_LEN * HH];
__device__ float g_Pout[S_LEN * HH];
__device__ float g_m[S_LEN * D_DIM];
__device__ float g_coeff[S_LEN];
__device__ float g_HHAT[2 * HH];

// ---------------- small PTX helpers ----------------
__device__ __forceinline__ uint32_t smem_u32(const void* p) {
    return (uint32_t)__cvta_generic_to_shared(p);
}
__device__ __forceinline__ void mbar_init(uint32_t a, uint32_t cnt) {
    asm volatile("mbarrier.init.shared.b64 [%0], %1;" ::"r"(a), "r"(cnt) : "memory");
}
__device__ __forceinline__ uint32_t mapa_shared(uint32_t a, uint32_t rank) {
    uint32_t r;
    asm("mapa.shared::cluster.u32 %0, %1, %2;" : "=r"(r) : "r"(a), "r"(rank));
    return r;
}
__device__ __forceinline__ void remote_store_f32(uint32_t ra, float v) {
    asm volatile("st.shared::cluster.f32 [%0], %1;" ::"r"(ra), "f"(v) : "memory");
}
__device__ __forceinline__ void mbar_arrive_remote(uint32_t ra) {
    asm volatile("mbarrier.arrive.release.cluster.shared::cluster.b64 _, [%0];" ::"r"(ra) : "memory");
}
__device__ __forceinline__ void mbar_wait(uint32_t a, uint32_t parity) {
    uint32_t done;
    asm volatile(
        "{\n\t.reg .pred p;\n\t"
        "mbarrier.try_wait.parity.acquire.cluster.shared::cta.b64 p, [%1], %2;\n\t"
        "selp.b32 %0,1,0,p;\n\t}"
        : "=r"(done) : "r"(a), "r"(parity) : "memory");
    while (!done) {
        asm volatile(
            "{\n\t.reg .pred p;\n\t"
            "mbarrier.try_wait.parity.acquire.cluster.shared::cta.b64 p, [%1], %2, 0x989680;\n\t"
            "selp.b32 %0,1,0,p;\n\t}"
            : "=r"(done) : "r"(a), "r"(parity) : "memory");
    }
}
__device__ __forceinline__ float fsig(float x) {
    return __fdividef(1.f, 1.f + __expf(-x));
}
__device__ __forceinline__ float ftanh(float x) {
    float e = __expf(2.f * x);
    return 1.f - __fdividef(2.f, e + 1.f);
}

// ---------------- embedding gather ----------------
__global__ void k_gather(const int* __restrict__ sentence, const float* __restrict__ E) {
    int s = blockIdx.x;
    const float* src = E + (size_t)sentence[s] * D_DIM;
    float* dst = g_emb + (size_t)s * D_DIM;
    for (int d = threadIdx.x; d < D_DIM; d += blockDim.x) dst[d] = src[d];
}

// ---------------- fp32 tiled GEMM: C[M,N] = A[M,K] @ B[K,N] + bias ----------------
#define BM 64
#define BN 64
#define BK 16

template <int M, int N, int K, int REV>
__device__ __forceinline__ void gemm_body(const float* __restrict__ A,
                                          const float* __restrict__ B,
                                          const float* __restrict__ bias,
                                          float* __restrict__ C) {
    __shared__ float As[BM][BK + 1];
    __shared__ float Bs[BK][BN];
    const int tx = threadIdx.x, ty = threadIdx.y;
    const int tid = ty * 16 + tx;
    const int m0 = blockIdx.y * BM, n0 = blockIdx.x * BN;

    float acc[4][4];
#pragma unroll
    for (int i = 0; i < 4; i++)
#pragma unroll
        for (int j = 0; j < 4; j++) acc[i][j] = 0.f;

    for (int k0 = 0; k0 < K; k0 += BK) {
#pragma unroll
        for (int l = 0; l < 4; l++) {
            int idx = tid + l * 256;
            int r = idx >> 4;
            int c = idx & 15;
            int gr = m0 + r;
            int gc = k0 + c;
            float v = 0.f;
            if (gc < K && gr < M) {
                int ar = REV ? (M - 1 - gr) : gr;
                v = A[(size_t)ar * K + gc];
            }
            As[r][c] = v;
        }
#pragma unroll
        for (int l = 0; l < 4; l++) {
            int idx = tid + l * 256;
            int r = idx >> 6;
            int c = idx & 63;
            int gk = k0 + r, gn = n0 + c;
            float v = 0.f;
            if (gk < K && gn < N) v = B[(size_t)gk * N + gn];
            Bs[r][c] = v;
        }
        __syncthreads();
#pragma unroll
        for (int kk = 0; kk < BK; kk++) {
            float a0 = As[ty * 4 + 0][kk];
            float a1 = As[ty * 4 + 1][kk];
            float a2 = As[ty * 4 + 2][kk];
            float a3 = As[ty * 4 + 3][kk];
            float4 b4 = *reinterpret_cast<const float4*>(&Bs[kk][tx * 4]);
            acc[0][0] = fmaf(a0, b4.x, acc[0][0]); acc[0][1] = fmaf(a0, b4.y, acc[0][1]);
            acc[0][2] = fmaf(a0, b4.z, acc[0][2]); acc[0][3] = fmaf(a0, b4.w, acc[0][3]);
            acc[1][0] = fmaf(a1, b4.x, acc[1][0]); acc[1][1] = fmaf(a1, b4.y, acc[1][1]);
            acc[1][2] = fmaf(a1, b4.z, acc[1][2]); acc[1][3] = fmaf(a1, b4.w, acc[1][3]);
            acc[2][0] = fmaf(a2, b4.x, acc[2][0]); acc[2][1] = fmaf(a2, b4.y, acc[2][1]);
            acc[2][2] = fmaf(a2, b4.z, acc[2][2]); acc[2][3] = fmaf(a2, b4.w, acc[2][3]);
            acc[3][0] = fmaf(a3, b4.x, acc[3][0]); acc[3][1] = fmaf(a3, b4.y, acc[3][1]);
            acc[3][2] = fmaf(a3, b4.z, acc[3][2]); acc[3][3] = fmaf(a3, b4.w, acc[3][3]);
        }
        __syncthreads();
    }
#pragma unroll
    for (int i = 0; i < 4; i++) {
        int gr = m0 + ty * 4 + i;
        if (gr < M) {
#pragma unroll
            for (int j = 0; j < 4; j++) {
                int gn = n0 + tx * 4 + j;
                if (gn < N) C[(size_t)gr * N + gn] = acc[i][j] + bias[gn];
            }
        }
    }
}

__global__ void k_gemm_Zf(const float* __restrict__ W, const float* __restrict__ b) {
    gemm_body<S_LEN, Z_DIM, D_DIM, 0>(g_emb, W, b, g_Zf);
}
__global__ void k_gemm_Zb(const float* __restrict__ W, const float* __restrict__ b) {
    gemm_body<S_LEN, Z_DIM, D_DIM, 1>(g_emb, W, b, g_Zb);
}
__global__ void k_gemm_P(const float* __restrict__ W, const float* __restrict__ b) {
    gemm_body<S_LEN, HH, HH, 0>(g_hidden, W, b, g_Pout);
}

// ---------------- LSTM recurrence: 2 clusters (fwd/bwd) of 6 CTAs ----------------
// Unit-major: output (u,g) handled by 4 lanes; unit u's 4 gates = 16 contiguous lanes.
// Cross-CTA sync: per-buffer mbarrier, expected = 150 arrives (25 owners x 6 CTAs).
#define GCL    6     // CTAs per cluster
#define UPC    25    // units per CTA
#define OPC    100   // gate outputs per CTA (4*25)
#define KCH    40    // k-chunk per lane (4*40 >= 150)
#define LSTM_T 416   // 400 active + pad to 13 warps
#define HPAD   160

__global__ __launch_bounds__(LSTM_T, 1) __cluster_dims__(GCL, 1, 1)
void k_lstm(const float* __restrict__ Uf, const float* __restrict__ Ub) {
    cg::cluster_group cluster = cg::this_cluster();
    const int rank = (int)cluster.block_rank();
    const int dir = blockIdx.x / GCL;  // 0 = fwd, 1 = bwd
    const float* __restrict__ Z = (dir == 0) ? g_Zf : g_Zb;
    const float* __restrict__ U = (dir == 0) ? Uf : Ub;

    __shared__ float h_sh[2][HPAD];           // double-buffered h (150 used, pad=0)
    __shared__ __align__(8) uint64_t full_mbar[2];

    const int tid = threadIdx.x;
    const int o_local = tid >> 2;             // 0..103
    const int lg = tid & 3;
    const bool active = (o_local < OPC);
    const int u = o_local >> 2;               // unit 0..24 (when active)
    const int g = o_local & 3;                // gate 0..3 (i,f,g,o)
    int j = g * HU + rank * UPC + u;          // column in [0,600)
    if (!active) j = 0;
    const int k0 = lg * KCH;
    const bool owner = active && ((tid & 15) == 0);  // lg==0 && g==0

    // U slice resident in registers (zeros beyond HU)
    float Ureg[KCH];
#pragma unroll
    for (int i = 0; i < KCH; i++) {
        int k = k0 + i;
        Ureg[i] = (active && k < HU) ? U[(size_t)k * Z_DIM + j] : 0.f;
    }

    for (int k = tid; k < HPAD; k += blockDim.x) { h_sh[0][k] = 0.f; h_sh[1][k] = 0.f; }

    const uint32_t fa0 = smem_u32(&full_mbar[0]);
    const uint32_t fa1 = smem_u32(&full_mbar[1]);
    const uint32_t hbase = smem_u32(&h_sh[0][0]);
    if (tid == 0) {
        mbar_init(fa0, GCL * UPC);
        mbar_init(fa1, GCL * UPC);
    }

    // owner-side precomputed remote addresses
    uint32_t peer_h[GCL], peer_f0[GCL], peer_f1[GCL];
    if (owner) {
#pragma unroll
        for (int r = 0; r < GCL; r++) {
            peer_h[r] = mapa_shared(hbase, r);
            peer_f0[r] = mapa_shared(fa0, r);
            peer_f1[r] = mapa_shared(fa1, r);
        }
    }
    const uint32_t slot_off = (uint32_t)(rank * UPC + u) * 4u;  // byte offset of h slot

    float c = 0.f;
    int phase0 = 0, phase1 = 0;

    cluster.sync();  // mbar init + zeroed buffers visible cluster-wide

    // prefetch Z row for t=0 (held by lg==0 lanes)
    float zcur = (active && lg == 0) ? __ldg(&Z[j]) : 0.f;

    for (int t = 0; t < S_LEN; t++) {
        const int b = t & 1;
        if (t) {
            if (b) { mbar_wait(fa1, phase1); phase1 ^= 1; }
            else   { mbar_wait(fa0, phase0); phase0 ^= 1; }
        }
        const float* hs = h_sh[b];
        float a0 = 0.f, a1 = 0.f, a2 = 0.f, a3 = 0.f;
#pragma unroll
        for (int i = 0; i < KCH / 4; i++) {
            float4 hv = *reinterpret_cast<const float4*>(&hs[k0 + i * 4]);
            a0 = fmaf(Ureg[4 * i + 0], hv.x, a0);
            a1 = fmaf(Ureg[4 * i + 1], hv.y, a1);
            a2 = fmaf(Ureg[4 * i + 2], hv.z, a2);
            a3 = fmaf(Ureg[4 * i + 3], hv.w, a3);
        }
        float acc = (a0 + a1) + (a2 + a3);
        acc += __shfl_xor_sync(0xffffffffu, acc, 1);
        acc += __shfl_xor_sync(0xffffffffu, acc, 2);
        float zfull = zcur + acc;  // meaningful on lg==0 lanes
        // prefetch next Z (independent load, hidden behind this step)
        if (active && lg == 0 && t + 1 < S_LEN) zcur = __ldg(&Z[(size_t)(t + 1) * Z_DIM + j]);

        // collect the 4 gate pre-activations onto the owner lane
        const int base = (tid & 31) & 16;
        float z1v = __shfl_sync(0xffffffffu, zfull, base + 4);
        float z2v = __shfl_sync(0xffffffffu, zfull, base + 8);
        float z3v = __shfl_sync(0xffffffffu, zfull, base + 12);
        __syncwarp();  // order this warp's h_sh reads before owner's release-arrive

        if (owner) {
            float ig = fsig(zfull);
            float fg = fsig(z1v);
            float gg = ftanh(z2v);
            float og = fsig(z3v);
            c = fg * c + ig * gg;
            float h = og * ftanh(c);
            int s_out = (dir == 0) ? t : (S_LEN - 1 - t);
            g_hidden[(size_t)s_out * HH + dir * HU + rank * UPC + u] = h;
            if (t + 1 < S_LEN) {
                const uint32_t boff = (uint32_t)((t + 1) & 1) * (HPAD * 4u) + slot_off;
#pragma unroll
                for (int r = 0; r < GCL; r++) remote_store_f32(peer_h[r] + boff, h);
                if ((t + 1) & 1) {
#pragma unroll
                    for (int r = 0; r < GCL; r++) mbar_arrive_remote(peer_f1[r]);
                } else {
#pragma unroll
                    for (int r = 0; r < GCL; r++) mbar_arrive_remote(peer_f0[r]);
                }
            }
        }
    }
}

// ---------------- primary attention (per word) + secondary attention coeff ----------------
__global__ void k_attn(const int* __restrict__ syn, const float* __restrict__ E,
                       const float* __restrict__ Ws, const float* __restrict__ bs) {
    int s = blockIdx.x;
    int tid = threadIdx.x;  // 128
    int warp = tid >> 5, lane = tid & 31;
    __shared__ float sc[NSYN];
    __shared__ int idx[NSYN];
    __shared__ float red[128];
    if (s == 0) {  // zero the H_HAT accumulator (consumed by k_hhat after this kernel)
        for (int k = tid; k < 2 * HH; k += 128) g_HHAT[k] = 0.f;
    }
    if (tid < NSYN) idx[tid] = syn[s * NSYN + tid];
    __syncthreads();
    {
        const float* sy = E + (size_t)idx[warp] * D_DIM;
        const float* po = g_Pout + (size_t)s * HH;
        float d0 = 0.f;
        for (int d = lane; d < D_DIM; d += 32) d0 = fmaf(po[d], sy[d], d0);
#pragma unroll
        for (int o = 16; o; o >>= 1) d0 += __shfl_xor_sync(0xffffffffu, d0, o);
        if (lane == 0) sc[warp] = __expf(d0);
    }
    __syncthreads();
    const float* e0 = E + (size_t)idx[0] * D_DIM;
    const float* e1 = E + (size_t)idx[1] * D_DIM;
    const float* e2 = E + (size_t)idx[2] * D_DIM;
    const float* e3 = E + (size_t)idx[3] * D_DIM;
    float s0 = sc[0], s1 = sc[1], s2 = sc[2], s3 = sc[3];
    float ca = 0.f;
    for (int d = tid; d < D_DIM; d += 128) {
        float md = s0 * e0[d] + s1 * e1[d] + s2 * e2[d] + s3 * e3[d];
        g_m[(size_t)s * D_DIM + d] = md;
        ca = fmaf(md, Ws[HH + d], ca);
        ca = fmaf(g_hidden[(size_t)s * HH + d], Ws[d], ca);
    }
    red[tid] = ca;
    __syncthreads();
    for (int o = 64; o; o >>= 1) {
        if (tid < o) red[tid] += red[tid + o];
        __syncthreads();
    }
    if (tid == 0) g_coeff[s] = __expf(tanhf(red[0] + bs[0]));
}

// ---------------- H_HAT[j] = sum_s coeff[s] * h_hats[s][j]  (parallel over s) ----------------
#define HH_BLOCKS 64
#define HH_SPB (S_LEN / HH_BLOCKS)
__global__ void k_hhat() {
    int jj = threadIdx.x;  // 0..599
    int s0 = blockIdx.x * HH_SPB;
    const float* src = (jj < HH) ? (g_hidden + jj) : (g_m + (jj - HH));
    float acc = 0.f;
#pragma unroll 4
    for (int s = s0; s < s0 + HH_SPB; s++)
        acc = fmaf(g_coeff[s], src[(size_t)s * HH], acc);
    atomicAdd(&g_HHAT[jj], acc);
}

// ---------------- output heads ----------------
__global__ void k_heads(const float* __restrict__ We, const float* __restrict__ be,
                        const float* __restrict__ Wse, const float* __restrict__ bse,
                        float* __restrict__ out) {
    int tid = threadIdx.x;
    if (tid < 8) {
        float a = 0.f;
        for (int jj = 0; jj < 2 * HH; jj++) a = fmaf(g_HHAT[jj], We[jj * 8 + tid], a);
        out[tid] = a + be[tid];
    } else if (tid == 8) {
        float a = 0.f;
        for (int jj = 0; jj < 2 * HH; jj++) a = fmaf(g_HHAT[jj], Wse[jj], a);
        out[8] = a + bse[0];
    }
}

// ---------------- launch ----------------
extern "C" void kernel_launch(void* const* d_in, const int* in_sizes, int n_in,
                              void* d_out, int out_size) {
    const int* sentence = (const int*)d_in[0];
    const int* syn = (const int*)d_in[1];
    const float* E = (const float*)d_in[2];
    const float* W_f = (const float*)d_in[3];
    const float* U_f = (const float*)d_in[4];
    const float* b_f = (const float*)d_in[5];
    const float* W_b = (const float*)d_in[6];
    const float* U_b = (const float*)d_in[7];
    const float* b_b = (const float*)d_in[8];
    const float* W_p = (const float*)d_in[9];
    const float* b_p = (const float*)d_in[10];
    const float* W_s = (const float*)d_in[11];
    const float* b_s = (const float*)d_in[12];
    const float* W_emo = (const float*)d_in[13];
    const float* b_emo = (const float*)d_in[14];
    const float* W_sent = (const float*)d_in[15];
    const float* b_sent = (const float*)d_in[16];
    float* out = (float*)d_out;

    k_gather<<<S_LEN, 128>>>(sentence, E);

    dim3 blk(16, 16);
    dim3 gz((Z_DIM + BN - 1) / BN, (S_LEN + BM - 1) / BM);
    k_gemm_Zf<<<gz, blk>>>(W_f, b_f);
    k_gemm_Zb<<<gz, blk>>>(W_b, b_b);

    k_lstm<<<2 * GCL, LSTM_T>>>(U_f, U_b);

    dim3 gp((HH + BN - 1) / BN, (S_LEN + BM - 1) / BM);
    k_gemm_P<<<gp, blk>>>(W_p, b_p);

    k_attn<<<S_LEN, 128>>>(syn, E, W_s, b_s);
    k_hhat<<<HH_BLOCKS, 2 * HH>>>();
    k_heads<<<1, 32>>>(W_emo, b_emo, W_sent, b_sent, out);
}

// round 4
// speedup vs baseline: 1.7226x; 1.7226x over previous
#include <cuda_runtime.h>
#include <cooperative_groups.h>
#include <math.h>
#include <stdint.h>

namespace cg = cooperative_groups;

#define S_LEN 4096
#define D_DIM 300
#define HU    150
#define HH    300      // biLSTM concat dim
#define Z_DIM 600      // 4*HU
#define NSYN  4

// ---------------- scratch (static device memory; no allocation) ----------------
__device__ float g_emb[S_LEN * D_DIM];
__device__ float g_Zf[S_LEN * Z_DIM];
__device__ float g_Zb[S_LEN * Z_DIM];
__device__ float g_hidden[S_LEN * HH];
__device__ float g_Pout[S_LEN * HH];
__device__ float g_m[S_LEN * D_DIM];
__device__ float g_coeff[S_LEN];
__device__ float g_HHAT[2 * HH];

// ---------------- small PTX helpers ----------------
__device__ __forceinline__ uint32_t smem_u32(const void* p) {
    return (uint32_t)__cvta_generic_to_shared(p);
}
__device__ __forceinline__ void mbar_init(uint32_t a, uint32_t cnt) {
    asm volatile("mbarrier.init.shared.b64 [%0], %1;" ::"r"(a), "r"(cnt) : "memory");
}
__device__ __forceinline__ uint32_t mapa_shared(uint32_t a, uint32_t rank) {
    uint32_t r;
    asm("mapa.shared::cluster.u32 %0, %1, %2;" : "=r"(r) : "r"(a), "r"(rank));
    return r;
}
__device__ __forceinline__ void remote_store_f32(uint32_t ra, float v) {
    asm volatile("st.shared::cluster.f32 [%0], %1;" ::"r"(ra), "f"(v) : "memory");
}
__device__ __forceinline__ void mbar_arrive_remote(uint32_t ra) {
    asm volatile("mbarrier.arrive.release.cluster.shared::cluster.b64 _, [%0];" ::"r"(ra) : "memory");
}
__device__ __forceinline__ void mbar_wait(uint32_t a, uint32_t parity) {
    uint32_t done;
    asm volatile(
        "{\n\t.reg .pred p;\n\t"
        "mbarrier.try_wait.parity.acquire.cluster.shared::cta.b64 p, [%1], %2;\n\t"
        "selp.b32 %0,1,0,p;\n\t}"
        : "=r"(done) : "r"(a), "r"(parity) : "memory");
    while (!done) {
        asm volatile(
            "{\n\t.reg .pred p;\n\t"
            "mbarrier.try_wait.parity.acquire.cluster.shared::cta.b64 p, [%1], %2, 0x989680;\n\t"
            "selp.b32 %0,1,0,p;\n\t}"
            : "=r"(done) : "r"(a), "r"(parity) : "memory");
    }
}
__device__ __forceinline__ float fsig(float x) {
    return __fdividef(1.f, 1.f + __expf(-x));
}
__device__ __forceinline__ float ftanh(float x) {
    float e = __expf(2.f * x);
    return 1.f - __fdividef(2.f, e + 1.f);
}

// ---------------- embedding gather ----------------
__global__ void k_gather(const int* __restrict__ sentence, const float* __restrict__ E) {
    int s = blockIdx.x;
    const float* src = E + (size_t)sentence[s] * D_DIM;
    float* dst = g_emb + (size_t)s * D_DIM;
    for (int d = threadIdx.x; d < D_DIM; d += blockDim.x) dst[d] = src[d];
}

// ---------------- fp32 tiled GEMM: C[M,N] = A[M,K] @ B[K,N] + bias ----------------
#define BM 64
#define BN 64
#define BK 16

template <int M, int N, int K, int REV>
__device__ __forceinline__ void gemm_body(const float* __restrict__ A,
                                          const float* __restrict__ B,
                                          const float* __restrict__ bias,
                                          float* __restrict__ C) {
    __shared__ float As[BM][BK + 1];
    __shared__ float Bs[BK][BN];
    const int tx = threadIdx.x, ty = threadIdx.y;
    const int tid = ty * 16 + tx;
    const int m0 = blockIdx.y * BM, n0 = blockIdx.x * BN;

    float acc[4][4];
#pragma unroll
    for (int i = 0; i < 4; i++)
#pragma unroll
        for (int j = 0; j < 4; j++) acc[i][j] = 0.f;

    for (int k0 = 0; k0 < K; k0 += BK) {
#pragma unroll
        for (int l = 0; l < 4; l++) {
            int idx = tid + l * 256;
            int r = idx >> 4;
            int c = idx & 15;
            int gr = m0 + r;
            int gc = k0 + c;
            float v = 0.f;
            if (gc < K && gr < M) {
                int ar = REV ? (M - 1 - gr) : gr;
                v = A[(size_t)ar * K + gc];
            }
            As[r][c] = v;
        }
#pragma unroll
        for (int l = 0; l < 4; l++) {
            int idx = tid + l * 256;
            int r = idx >> 6;
            int c = idx & 63;
            int gk = k0 + r, gn = n0 + c;
            float v = 0.f;
            if (gk < K && gn < N) v = B[(size_t)gk * N + gn];
            Bs[r][c] = v;
        }
        __syncthreads();
#pragma unroll
        for (int kk = 0; kk < BK; kk++) {
            float a0 = As[ty * 4 + 0][kk];
            float a1 = As[ty * 4 + 1][kk];
            float a2 = As[ty * 4 + 2][kk];
            float a3 = As[ty * 4 + 3][kk];
            float4 b4 = *reinterpret_cast<const float4*>(&Bs[kk][tx * 4]);
            acc[0][0] = fmaf(a0, b4.x, acc[0][0]); acc[0][1] = fmaf(a0, b4.y, acc[0][1]);
            acc[0][2] = fmaf(a0, b4.z, acc[0][2]); acc[0][3] = fmaf(a0, b4.w, acc[0][3]);
            acc[1][0] = fmaf(a1, b4.x, acc[1][0]); acc[1][1] = fmaf(a1, b4.y, acc[1][1]);
            acc[1][2] = fmaf(a1, b4.z, acc[1][2]); acc[1][3] = fmaf(a1, b4.w, acc[1][3]);
            acc[2][0] = fmaf(a2, b4.x, acc[2][0]); acc[2][1] = fmaf(a2, b4.y, acc[2][1]);
            acc[2][2] = fmaf(a2, b4.z, acc[2][2]); acc[2][3] = fmaf(a2, b4.w, acc[2][3]);
            acc[3][0] = fmaf(a3, b4.x, acc[3][0]); acc[3][1] = fmaf(a3, b4.y, acc[3][1]);
            acc[3][2] = fmaf(a3, b4.z, acc[3][2]); acc[3][3] = fmaf(a3, b4.w, acc[3][3]);
        }
        __syncthreads();
    }
#pragma unroll
    for (int i = 0; i < 4; i++) {
        int gr = m0 + ty * 4 + i;
        if (gr < M) {
#pragma unroll
            for (int j = 0; j < 4; j++) {
                int gn = n0 + tx * 4 + j;
                if (gn < N) C[(size_t)gr * N + gn] = acc[i][j] + bias[gn];
            }
        }
    }
}

__global__ void k_gemm_Zf(const float* __restrict__ W, const float* __restrict__ b) {
    gemm_body<S_LEN, Z_DIM, D_DIM, 0>(g_emb, W, b, g_Zf);
}
__global__ void k_gemm_Zb(const float* __restrict__ W, const float* __restrict__ b) {
    gemm_body<S_LEN, Z_DIM, D_DIM, 1>(g_emb, W, b, g_Zb);
}
__global__ void k_gemm_P(const float* __restrict__ W, const float* __restrict__ b) {
    gemm_body<S_LEN, HH, HH, 0>(g_hidden, W, b, g_Pout);
}

// ---------------- LSTM recurrence: 2 clusters (fwd/bwd) of 6 CTAs ----------------
// Unit-major: output (u,g) handled by 4 lanes; unit u's 4 gates = 16 contiguous lanes.
// Cross-CTA sync per step: owners remote-store h; local bar.sync; 6 threads issue ONE
// remote arrive each (expected = 6 per mbarrier); next step begins with local wait.
#define GCL    6     // CTAs per cluster
#define UPC    25    // units per CTA
#define OPC    100   // gate outputs per CTA (4*25)
#define KCH    40    // k-chunk per lane (4*40 >= 150)
#define LSTM_T 416   // 400 active + pad to 13 warps
#define HPAD   160

__global__ __launch_bounds__(LSTM_T, 1) __cluster_dims__(GCL, 1, 1)
void k_lstm(const float* __restrict__ Uf, const float* __restrict__ Ub) {
    cg::cluster_group cluster = cg::this_cluster();
    const int rank = (int)cluster.block_rank();
    const int dir = blockIdx.x / GCL;  // 0 = fwd, 1 = bwd
    const float* __restrict__ Z = (dir == 0) ? g_Zf : g_Zb;
    const float* __restrict__ U = (dir == 0) ? Uf : Ub;

    __shared__ float h_sh[2][HPAD];           // double-buffered h (150 used, pad=0)
    __shared__ __align__(8) uint64_t full_mbar[2];

    const int tid = threadIdx.x;
    const int o_local = tid >> 2;             // 0..103
    const int lg = tid & 3;
    const bool active = (o_local < OPC);
    const int u = o_local >> 2;               // unit 0..24 (when active)
    const int g = o_local & 3;                // gate 0..3 (i,f,g,o)
    int j = g * HU + rank * UPC + u;          // column in [0,600)
    if (!active) j = 0;
    const int k0 = lg * KCH;
    const bool owner = active && ((tid & 15) == 0);  // lg==0 && g==0

    // U slice resident in registers (zeros beyond HU)
    float Ureg[KCH];
#pragma unroll
    for (int i = 0; i < KCH; i++) {
        int k = k0 + i;
        Ureg[i] = (active && k < HU) ? U[(size_t)k * Z_DIM + j] : 0.f;
    }

    for (int k = tid; k < HPAD; k += blockDim.x) { h_sh[0][k] = 0.f; h_sh[1][k] = 0.f; }

    const uint32_t fa0 = smem_u32(&full_mbar[0]);
    const uint32_t fa1 = smem_u32(&full_mbar[1]);
    const uint32_t hbase = smem_u32(&h_sh[0][0]);
    if (tid == 0) {
        mbar_init(fa0, GCL);
        mbar_init(fa1, GCL);
    }

    // owner-side precomputed remote h-slot addresses (both buffers)
    uint32_t peer_hA[GCL], peer_hB[GCL];
    if (owner) {
        const uint32_t slot_off = (uint32_t)(rank * UPC + u) * 4u;
#pragma unroll
        for (int r = 0; r < GCL; r++) {
            uint32_t base = mapa_shared(hbase, r);
            peer_hA[r] = base + slot_off;
            peer_hB[r] = base + slot_off + HPAD * 4u;
        }
    }
    // arrive-side: thread tid<GCL targets CTA 'tid'
    uint32_t arr_f0 = 0, arr_f1 = 0;
    if (tid < GCL) {
        arr_f0 = mapa_shared(fa0, tid);
        arr_f1 = mapa_shared(fa1, tid);
    }

    float c = 0.f;
    int phase0 = 0, phase1 = 0;

    cluster.sync();  // mbar init + zeroed buffers visible cluster-wide

    // prefetch Z row for t=0 (held by lg==0 lanes)
    float zcur = (active && lg == 0) ? __ldg(&Z[j]) : 0.f;

    for (int t = 0; t < S_LEN; t++) {
        const int b = t & 1;
        if (t) {
            if (b) { mbar_wait(fa1, phase1); phase1 ^= 1; }
            else   { mbar_wait(fa0, phase0); phase0 ^= 1; }
        }
        const float* hs = h_sh[b];
        float a0 = 0.f, a1 = 0.f, a2 = 0.f, a3 = 0.f;
#pragma unroll
        for (int i = 0; i < KCH / 4; i++) {
            float4 hv = *reinterpret_cast<const float4*>(&hs[k0 + i * 4]);
            a0 = fmaf(Ureg[4 * i + 0], hv.x, a0);
            a1 = fmaf(Ureg[4 * i + 1], hv.y, a1);
            a2 = fmaf(Ureg[4 * i + 2], hv.z, a2);
            a3 = fmaf(Ureg[4 * i + 3], hv.w, a3);
        }
        float acc = (a0 + a1) + (a2 + a3);
        acc += __shfl_xor_sync(0xffffffffu, acc, 1);
        acc += __shfl_xor_sync(0xffffffffu, acc, 2);
        float zfull = zcur + acc;  // meaningful on lg==0 lanes
        // prefetch next Z (independent load, hidden behind this step)
        if (active && lg == 0 && t + 1 < S_LEN) zcur = __ldg(&Z[(size_t)(t + 1) * Z_DIM + j]);

        // each lg==0 lane computes its own gate activation (off the owner's chain)
        float act = 0.f;
        if (active && lg == 0) act = (g == 2) ? ftanh(zfull) : fsig(zfull);

        // collect activated gates onto the owner lane (unit's lanes at base+0/4/8/12)
        const int base = (tid & 31) & 16;
        float fg = __shfl_sync(0xffffffffu, act, base + 4);
        float gg = __shfl_sync(0xffffffffu, act, base + 8);
        float og = __shfl_sync(0xffffffffu, act, base + 12);

        if (owner) {
            c = fg * c + act * gg;
            float h = og * ftanh(c);
            int s_out = (dir == 0) ? t : (S_LEN - 1 - t);
            g_hidden[(size_t)s_out * HH + dir * HU + rank * UPC + u] = h;
            if (t + 1 < S_LEN) {
                if ((t + 1) & 1) {
#pragma unroll
                    for (int r = 0; r < GCL; r++) remote_store_f32(peer_hB[r], h);
                } else {
#pragma unroll
                    for (int r = 0; r < GCL; r++) remote_store_f32(peer_hA[r], h);
                }
            }
        }
        // one local barrier: orders ALL threads' reads of buf b and owners' remote
        // stores of buf b^1 before the aggregated cluster arrives below
        __syncthreads();
        if (tid < GCL && t + 1 < S_LEN) {
            if ((t + 1) & 1) mbar_arrive_remote(arr_f1);
            else             mbar_arrive_remote(arr_f0);
        }
    }
}

// ---------------- primary attention (per word) + secondary attention coeff ----------------
__global__ void k_attn(const int* __restrict__ syn, const float* __restrict__ E,
                       const float* __restrict__ Ws, const float* __restrict__ bs) {
    int s = blockIdx.x;
    int tid = threadIdx.x;  // 128
    int warp = tid >> 5, lane = tid & 31;
    __shared__ float sc[NSYN];
    __shared__ int idx[NSYN];
    __shared__ float red[128];
    if (s == 0) {  // zero the H_HAT accumulator (consumed by k_hhat after this kernel)
        for (int k = tid; k < 2 * HH; k += 128) g_HHAT[k] = 0.f;
    }
    if (tid < NSYN) idx[tid] = syn[s * NSYN + tid];
    __syncthreads();
    {
        const float* sy = E + (size_t)idx[warp] * D_DIM;
        const float* po = g_Pout + (size_t)s * HH;
        float d0 = 0.f;
        for (int d = lane; d < D_DIM; d += 32) d0 = fmaf(po[d], sy[d], d0);
#pragma unroll
        for (int o = 16; o; o >>= 1) d0 += __shfl_xor_sync(0xffffffffu, d0, o);
        if (lane == 0) sc[warp] = __expf(d0);
    }
    __syncthreads();
    const float* e0 = E + (size_t)idx[0] * D_DIM;
    const float* e1 = E + (size_t)idx[1] * D_DIM;
    const float* e2 = E + (size_t)idx[2] * D_DIM;
    const float* e3 = E + (size_t)idx[3] * D_DIM;
    float s0 = sc[0], s1 = sc[1], s2 = sc[2], s3 = sc[3];
    float ca = 0.f;
    for (int d = tid; d < D_DIM; d += 128) {
        float md = s0 * e0[d] + s1 * e1[d] + s2 * e2[d] + s3 * e3[d];
        g_m[(size_t)s * D_DIM + d] = md;
        ca = fmaf(md, Ws[HH + d], ca);
        ca = fmaf(g_hidden[(size_t)s * HH + d], Ws[d], ca);
    }
    red[tid] = ca;
    __syncthreads();
    for (int o = 64; o; o >>= 1) {
        if (tid < o) red[tid] += red[tid + o];
        __syncthreads();
    }
    if (tid == 0) g_coeff[s] = __expf(tanhf(red[0] + bs[0]));
}

// ---------------- H_HAT[j] = sum_s coeff[s] * h_hats[s][j]  (parallel over s) ----------------
#define HH_BLOCKS 64
#define HH_SPB (S_LEN / HH_BLOCKS)
__global__ void k_hhat() {
    int jj = threadIdx.x;  // 0..599
    int s0 = blockIdx.x * HH_SPB;
    const float* src = (jj < HH) ? (g_hidden + jj) : (g_m + (jj - HH));
    float acc = 0.f;
#pragma unroll 4
    for (int s = s0; s < s0 + HH_SPB; s++)
        acc = fmaf(g_coeff[s], src[(size_t)s * HH], acc);
    atomicAdd(&g_HHAT[jj], acc);
}

// ---------------- output heads ----------------
__global__ void k_heads(const float* __restrict__ We, const float* __restrict__ be,
                        const float* __restrict__ Wse, const float* __restrict__ bse,
                        float* __restrict__ out) {
    int tid = threadIdx.x;
    if (tid < 8) {
        float a = 0.f;
        for (int jj = 0; jj < 2 * HH; jj++) a = fmaf(g_HHAT[jj], We[jj * 8 + tid], a);
        out[tid] = a + be[tid];
    } else if (tid == 8) {
        float a = 0.f;
        for (int jj = 0; jj < 2 * HH; jj++) a = fmaf(g_HHAT[jj], Wse[jj], a);
        out[8] = a + bse[0];
    }
}

// ---------------- launch ----------------
extern "C" void kernel_launch(void* const* d_in, const int* in_sizes, int n_in,
                              void* d_out, int out_size) {
    const int* sentence = (const int*)d_in[0];
    const int* syn = (const int*)d_in[1];
    const float* E = (const float*)d_in[2];
    const float* W_f = (const float*)d_in[3];
    const float* U_f = (const float*)d_in[4];
    const float* b_f = (const float*)d_in[5];
    const float* W_b = (const float*)d_in[6];
    const float* U_b = (const float*)d_in[7];
    const float* b_b = (const float*)d_in[8];
    const float* W_p = (const float*)d_in[9];
    const float* b_p = (const float*)d_in[10];
    const float* W_s = (const float*)d_in[11];
    const float* b_s = (const float*)d_in[12];
    const float* W_emo = (const float*)d_in[13];
    const float* b_emo = (const float*)d_in[14];
    const float* W_sent = (const float*)d_in[15];
    const float* b_sent = (const float*)d_in[16];
    float* out = (float*)d_out;

    k_gather<<<S_LEN, 128>>>(sentence, E);

    dim3 blk(16, 16);
    dim3 gz((Z_DIM + BN - 1) / BN, (S_LEN + BM - 1) / BM);
    k_gemm_Zf<<<gz, blk>>>(W_f, b_f);
    k_gemm_Zb<<<gz, blk>>>(W_b, b_b);

    k_lstm<<<2 * GCL, LSTM_T>>>(U_f, U_b);

    dim3 gp((HH + BN - 1) / BN, (S_LEN + BM - 1) / BM);
    k_gemm_P<<<gp, blk>>>(W_p, b_p);

    k_attn<<<S_LEN, 128>>>(syn, E, W_s, b_s);
    k_hhat<<<HH_BLOCKS, 2 * HH>>>();
    k_heads<<<1, 32>>>(W_emo, b_emo, W_sent, b_sent, out);
}